// round 1
// baseline (speedup 1.0000x reference)
#include <cuda_runtime.h>

// ---------------------------------------------------------------------------
// OneHotEncoding: for B receivers find nearest of L 2-D mesh points.
// Outputs (assumed concatenated float32 in d_out):
//   [0, 3L)            input_tensor rows (X, Y, one_hot)
//   [3L, 3L+2B)        closest_points (x, y per receiver)
//   [3L+2B, 3L+3B)     min_index as float
// All non-input_tensor writes are guarded by out_size.
// ---------------------------------------------------------------------------

#define TILE    1024
#define MAXBLK  2048
#define MAXB    512

// scratch for per-block partial argmins (device globals: no allocation allowed)
__device__ float g_pmin[MAXBLK * MAXB];
__device__ int   g_pidx[MAXBLK * MAXB];

__global__ void __launch_bounds__(256)
argmin_partial(const float* __restrict__ mesh,
               const float* __restrict__ recv,
               float* __restrict__ out,
               int L, int B)
{
    __shared__ float2 s_pts[TILE];

    const int blk = blockIdx.x;
    const int tid = threadIdx.x;
    const int p0  = blk * TILE;
    const int npts = min(TILE, L - p0);

    // Stage tile into SMEM; fuse the input_tensor row writes (X, Y, 0).
    for (int i = tid; i < npts; i += 256) {
        float2 p = reinterpret_cast<const float2*>(mesh)[p0 + i];
        s_pts[i] = p;
        const int r = p0 + i;
        out[3 * r + 0] = p.x;
        out[3 * r + 1] = p.y;
        out[3 * r + 2] = 0.0f;   // one_hot zeros; ones scattered by finalize
    }
    __syncthreads();

    float rx = 0.0f, ry = 0.0f;
    if (tid < B) {
        rx = recv[3 * tid + 0];
        ry = recv[3 * tid + 1];
    }

    float vmin = 3.402823e38f;
    int   imin = 0;

    // Each thread = one receiver, scans the whole tile (SMEM broadcast).
    // Strict '<' keeps the earliest index (ascending scan) to match argmin.
    #pragma unroll 4
    for (int i = 0; i < npts; i++) {
        const float dx = s_pts[i].x - rx;
        const float dy = s_pts[i].y - ry;
        const float v  = fmaf(dx, dx, dy * dy);
        if (v < vmin) { vmin = v; imin = p0 + i; }
    }

    if (tid < B) {
        g_pmin[blk * B + tid] = vmin;
        g_pidx[blk * B + tid] = imin;
    }
}

__global__ void __launch_bounds__(256)
argmin_finalize(const float* __restrict__ mesh,
                float* __restrict__ out,
                int L, int B, int nblk, long long out_size)
{
    const int b   = blockIdx.x;   // receiver id
    const int tid = threadIdx.x;

    float vmin = 3.402823e38f;
    int   imin = 0x7fffffff;
    for (int k = tid; k < nblk; k += 256) {
        const float v = g_pmin[k * B + b];
        const int   i = g_pidx[k * B + b];
        if (v < vmin || (v == vmin && i < imin)) { vmin = v; imin = i; }
    }

    __shared__ float sv[256];
    __shared__ int   si[256];
    sv[tid] = vmin;
    si[tid] = imin;
    __syncthreads();

    for (int s = 128; s > 0; s >>= 1) {
        if (tid < s) {
            const float v = sv[tid + s];
            const int   i = si[tid + s];
            if (v < sv[tid] || (v == sv[tid] && i < si[tid])) {
                sv[tid] = v; si[tid] = i;
            }
        }
        __syncthreads();
    }

    if (tid == 0) {
        const int mi = si[0];
        const long long base1 = 3LL * L;

        // one_hot scatter (duplicates benignly rewrite 1.0)
        out[3LL * mi + 2] = 1.0f;
        if (b == 0 && B > 1) out[2] = 1.0f;

        if (out_size >= base1 + 2LL * B) {
            out[base1 + 2LL * b + 0] = mesh[2 * mi + 0];
            out[base1 + 2LL * b + 1] = mesh[2 * mi + 1];
        }
        if (out_size >= base1 + 3LL * B) {
            out[base1 + 2LL * B + b] = (float)mi;
        }
    }
}

extern "C" void kernel_launch(void* const* d_in, const int* in_sizes, int n_in,
                              void* d_out, int out_size)
{
    const float* mesh = (const float*)d_in[0];
    const float* recv = (const float*)d_in[1];
    float* out = (float*)d_out;

    const int L = in_sizes[0] / 2;
    const int B = in_sizes[1] / 3;
    int nblk = (L + TILE - 1) / TILE;
    if (nblk > MAXBLK) nblk = MAXBLK;  // safety (L=1e6 -> 977 blocks)

    argmin_partial<<<nblk, 256>>>(mesh, recv, out, L, B);
    argmin_finalize<<<B, 256>>>(mesh, out, L, B, nblk, (long long)out_size);
}